// round 12
// baseline (speedup 1.0000x reference)
#include <cuda_runtime.h>
#include <cuda_bf16.h>

// RandomResizedCrop resample: out[i] = (1-w)*cropped[lo_c] + w*cropped[hi_c],
// idx = f32(i) * delta, delta = f32(crop_len-1)/f32(n-1) (= 0.875f here),
// lo_c/hi_c clamped to crop_len-1 (JAX gather clamp), w from UNclamped
// floor(idx). Matches reference to rel_err 6.9e-9.
//
// R11 base (35.8us: lane-consecutive gathers MLP~16, evict-last policy
// reads, __stcs stores, L2 prefetch one wave ahead -> DRAM 71%) with the
// prefetch stream deepened: each block prefetches the input window of
// blk+1184 AND blk+2368 (1 and 2 waves ahead, ~2.9/5.8us). Duplicate
// probes of present lines are near-free; ahead-depth doubles and the
// per-wave prefetch bursts overlap two generations, smoothing DRAM feed.

#define THREADS      256
#define OUT_PER_THR  8
#define OUT_TILE     (THREADS * OUT_PER_THR)   // 2048 outputs per block
#define PF_AHEAD     1184                      // one full wave of blocks
#define PF_LINES     56                        // 2048*0.875 floats = 56 x 128B

__device__ __forceinline__ unsigned long long make_evict_last_policy() {
    unsigned long long pol;
    asm volatile("createpolicy.fractional.L2::evict_last.b64 %0, 1.0;"
                 : "=l"(pol));
    return pol;
}

__device__ __forceinline__ float ldg_policy(const float* p, unsigned long long pol) {
    float v;
    asm volatile("ld.global.nc.L2::cache_hint.f32 %0, [%1], %2;"
                 : "=f"(v) : "l"(p), "l"(pol));
    return v;
}

__global__ __launch_bounds__(THREADS)
void resample_pf2_kernel(const float* __restrict__ audio,
                         const int* __restrict__ p_crop,
                         const int* __restrict__ p_start,
                         float* __restrict__ out,
                         int n, int audio_len) {
    const int crop_len = __ldg(p_crop);
    const int start    = __ldg(p_start);
    const float delta  = (float)(crop_len - 1) / (float)(n - 1);
    const int clampv   = crop_len - 1;
    const float* __restrict__ base = audio + start;
    const unsigned long long pol = make_evict_last_policy();

    // Dual-distance prefetch: window of block B starts near B*1792 floats
    // (2048*7/8); 1792 floats = 56 lines of 128 B. Threads 0..55 prefetch
    // one wave ahead, threads 56..111 two waves ahead. Clamped in-bounds.
    if (threadIdx.x < 2 * PF_LINES) {
        int which = (threadIdx.x < PF_LINES) ? 1 : 2;
        int lane  = (threadIdx.x < PF_LINES) ? (int)threadIdx.x
                                             : (int)threadIdx.x - PF_LINES;
        int b2  = blockIdx.x + which * PF_AHEAD;
        int pfi = b2 * 1792 + lane * 32 - 8;      // -8: fp32 rounding slack
        pfi = max(pfi, 0);
        pfi = min(start + pfi, audio_len - 1);
        asm volatile("prefetch.global.L2 [%0];" :: "l"(audio + pfi));
    }

    const int i0 = blockIdx.x * OUT_TILE + threadIdx.x;

    // Phase 1: indices/weights, issue all 16 gathers (independent, MLP~16).
    float a[OUT_PER_THR], b[OUT_PER_THR], w[OUT_PER_THR];
    #pragma unroll
    for (int k = 0; k < OUT_PER_THR; k++) {
        int i      = i0 + k * THREADS;
        float fi   = (float)i;         // RN convert (matches f32 iota rounding)
        float idx  = fi * delta;       // RN multiply (matches XLA linspace)
        int lo     = (int)floorf(idx);
        w[k]       = idx - (float)lo;  // from UNclamped lo (reference semantics)
        int lo_c   = min(lo,     clampv);   // JAX gather clamp
        int hi_c   = min(lo + 1, clampv);
        a[k]       = ldg_policy(base + lo_c, pol);
        b[k]       = ldg_policy(base + hi_c, pol);
    }

    // Phase 2: interpolate + evict-first stores (coalesced STG.32).
    #pragma unroll
    for (int k = 0; k < OUT_PER_THR; k++) {
        float v = (1.0f - w[k]) * a[k] + w[k] * b[k];
        __stcs(out + i0 + k * THREADS, v);
    }
}

extern "C" void kernel_launch(void* const* d_in, const int* in_sizes, int n_in,
                              void* d_out, int out_size) {
    const float* audio   = (const float*)d_in[0];
    const int*   p_crop  = (const int*)d_in[1];
    const int*   p_start = (const int*)d_in[2];
    float*       out     = (float*)d_out;

    const int n         = out_size;              // 2^25 (multiple of OUT_TILE)
    const int audio_len = in_sizes[0];
    const int blocks    = (n + OUT_TILE - 1) / OUT_TILE;   // 16384

    resample_pf2_kernel<<<blocks, THREADS>>>(audio, p_crop, p_start, out, n, audio_len);
}

// round 13
// speedup vs baseline: 1.0371x; 1.0371x over previous
#include <cuda_runtime.h>
#include <cuda_bf16.h>

// RandomResizedCrop resample: out[i] = (1-w)*cropped[lo_c] + w*cropped[hi_c],
// idx = f32(i) * delta, delta = f32(crop_len-1)/f32(n-1) (= 0.875f here),
// lo_c/hi_c clamped to crop_len-1 (JAX gather clamp), w from UNclamped
// floor(idx). Matches reference to rel_err 6.9e-9.
//
// R11 structure (best, 35.8us): lane-consecutive gathers MLP~16 per thread,
// evict-last policy reads, __stcs evict-first stores, single-distance L2
// prefetch of the input window one resident-set ahead (decouples the DRAM
// read stream from gather consumption; R12 showed a second prefetch stream
// only adds L1 cost). This round: 512-thread blocks — halves block count,
// halving per-block scalar setup (crop/start loads, createpolicy, divide)
// and CTA churn; prefetch coverage, op counts, occupancy, math unchanged.

#define THREADS      512
#define OUT_PER_THR  8
#define OUT_TILE     (THREADS * OUT_PER_THR)   // 4096 outputs per block
#define PF_AHEAD     592                       // ~one resident set (4 x 148)
#define PF_LINES     112                       // 4096*0.875 floats = 112 x 128B
#define WIN_FLOATS   3584                      // OUT_TILE * 7/8

__device__ __forceinline__ unsigned long long make_evict_last_policy() {
    unsigned long long pol;
    asm volatile("createpolicy.fractional.L2::evict_last.b64 %0, 1.0;"
                 : "=l"(pol));
    return pol;
}

__device__ __forceinline__ float ldg_policy(const float* p, unsigned long long pol) {
    float v;
    asm volatile("ld.global.nc.L2::cache_hint.f32 %0, [%1], %2;"
                 : "=f"(v) : "l"(p), "l"(pol));
    return v;
}

__global__ __launch_bounds__(THREADS)
void resample_pf512_kernel(const float* __restrict__ audio,
                           const int* __restrict__ p_crop,
                           const int* __restrict__ p_start,
                           float* __restrict__ out,
                           int n, int audio_len) {
    const int crop_len = __ldg(p_crop);
    const int start    = __ldg(p_start);
    const float delta  = (float)(crop_len - 1) / (float)(n - 1);
    const int clampv   = crop_len - 1;
    const float* __restrict__ base = audio + start;
    const unsigned long long pol = make_evict_last_policy();

    // Single-distance prefetch: input window of block (blk + PF_AHEAD)
    // starts near (blk+PF_AHEAD)*3584 floats; 112 lines of 128 B.
    if (threadIdx.x < PF_LINES) {
        int b2  = blockIdx.x + PF_AHEAD;
        int pfi = b2 * WIN_FLOATS + (int)threadIdx.x * 32 - 8;  // -8: fp32 slack
        pfi = max(pfi, 0);
        pfi = min(start + pfi, audio_len - 1);
        asm volatile("prefetch.global.L2 [%0];" :: "l"(audio + pfi));
    }

    const int i0 = blockIdx.x * OUT_TILE + threadIdx.x;

    // Phase 1: indices/weights, issue all 16 gathers (independent, MLP~16).
    float a[OUT_PER_THR], b[OUT_PER_THR], w[OUT_PER_THR];
    #pragma unroll
    for (int k = 0; k < OUT_PER_THR; k++) {
        int i      = i0 + k * THREADS;
        float fi   = (float)i;         // RN convert (matches f32 iota rounding)
        float idx  = fi * delta;       // RN multiply (matches XLA linspace)
        int lo     = (int)floorf(idx);
        w[k]       = idx - (float)lo;  // from UNclamped lo (reference semantics)
        int lo_c   = min(lo,     clampv);   // JAX gather clamp
        int hi_c   = min(lo + 1, clampv);
        a[k]       = ldg_policy(base + lo_c, pol);
        b[k]       = ldg_policy(base + hi_c, pol);
    }

    // Phase 2: interpolate + evict-first stores (coalesced STG.32).
    #pragma unroll
    for (int k = 0; k < OUT_PER_THR; k++) {
        float v = (1.0f - w[k]) * a[k] + w[k] * b[k];
        __stcs(out + i0 + k * THREADS, v);
    }
}

extern "C" void kernel_launch(void* const* d_in, const int* in_sizes, int n_in,
                              void* d_out, int out_size) {
    const float* audio   = (const float*)d_in[0];
    const int*   p_crop  = (const int*)d_in[1];
    const int*   p_start = (const int*)d_in[2];
    float*       out     = (float*)d_out;

    const int n         = out_size;              // 2^25 (multiple of OUT_TILE)
    const int audio_len = in_sizes[0];
    const int blocks    = (n + OUT_TILE - 1) / OUT_TILE;   // 4096

    resample_pf512_kernel<<<blocks, THREADS>>>(audio, p_crop, p_start, out, n, audio_len);
}